// round 12
// baseline (speedup 1.0000x reference)
#include <cuda_runtime.h>

// ============================================================================
// AdderNet TauNet R12: R9 structure (warp-per-quad E=4) with packed f32x2
// math (FFMA2/FADD2 + LOP3 abs) and pre-duplicated (w,w) weight tables.
// ============================================================================

typedef unsigned long long u64;

#define EPSV 1e-5f

// ---- s_small layout (floats), dynamic smem, all weights duplicated pairs ----
#define W1OFF   0      // 5 x 32   (16 taps x2)
#define W2OFF   160    // 50 x 24  (12 taps x2)
#define R1TOFF  1360   // 10 x 32
#define R2TOFF  1680   // 10 x 32
#define A1OFF   2000
#define B1OFF   2005
#define A2OFF   2010
#define B2OFF   2020
#define AR1OFF  2030
#define BR1OFF  2040
#define AR2OFF  2050
#define BR2OFF  2060
#define AOAOFF  2070   // 140
#define BOAOFF  2210   // 140
#define AOBOFF  2350   // 60
#define BOBOFF  2410   // 60
#define AOCOFF  2470   // 2
#define BOCOFF  2472   // 2
#define QOCOFF  2474   // 2 x 64 dup pairs
#define SMALL_N 2604   // 10416 B, 16B multiple

__device__ float g_small[2608];
__device__ float g_qoa2[2 * 35 * 70 * 8];   // [branch][i4][c][8] = (w,w) x4 taps
__device__ float g_qob2[2 * 18 * 30 * 8];

__device__ __forceinline__ float quantv(float w, float s) {
    float t = fminf(fmaxf(w / s, -127.f), 127.f);
    return rintf(t) * s;
}

__device__ __forceinline__ void fill_bn(const float* bn, int c, float* A, float* Bt) {
    for (int i = threadIdx.x; i < c; i += blockDim.x) {
        float g = bn[i], b = bn[c + i], m = bn[2 * c + i], v = bn[3 * c + i];
        float al = g * rsqrtf(v + EPSV);
        A[i] = al;
        Bt[i] = b - m * al;
    }
}

// ---------------------------------------------------------------------------
__global__ void setup_kernel(
    const float* __restrict__ w1,   const float* __restrict__ w2,
    const float* __restrict__ wr1,  const float* __restrict__ wr2,
    const float* __restrict__ wo1a, const float* __restrict__ wo1b, const float* __restrict__ wo1c,
    const float* __restrict__ wo2a, const float* __restrict__ wo2b, const float* __restrict__ wo2c,
    const float* __restrict__ bn1,  const float* __restrict__ bn2,
    const float* __restrict__ bnr1, const float* __restrict__ bnr2,
    const float* __restrict__ bno1a, const float* __restrict__ bno1b, const float* __restrict__ bno1c,
    const float* __restrict__ bno2a, const float* __restrict__ bno2b, const float* __restrict__ bno2c)
{
    const int blk = blockIdx.x, tid = threadIdx.x;
    if (blk < 10) {
        const float* w; int n;
        switch (blk) {
            case 0: w = w1;   n = 65;   break;
            case 1: w = w2;   n = 450;  break;
            case 2: w = wr1;  n = 100;  break;
            case 3: w = wr2;  n = 100;  break;
            case 4: case 5: w = wo1a; n = 9800; break;
            case 6: case 7: w = wo2a; n = 9800; break;
            case 8: w = wo1b; n = 2100; break;
            default: w = wo2b; n = 2100; break;
        }
        __shared__ float red[256];
        float m = 0.f;
        for (int i = tid; i < n; i += 256) m = fmaxf(m, fabsf(w[i]));
        red[tid] = m;
        __syncthreads();
        for (int s = 128; s > 0; s >>= 1) {
            if (tid < s) red[tid] = fmaxf(red[tid], red[tid + s]);
            __syncthreads();
        }
        const float s = red[0] / 127.f;

        if (blk == 0) {
            for (int j = tid; j < 160; j += 256) {
                int c = j >> 5, k = (j & 31) >> 1;
                g_small[W1OFF + j] = (k < 13) ? quantv(w[c * 13 + k], s) : 0.f;
            }
        } else if (blk == 1) {
            for (int j = tid; j < 1200; j += 256) {
                int row = j / 24, k = (j % 24) >> 1;
                g_small[W2OFF + j] = (k < 9) ? quantv(w[row * 9 + k], s) : 0.f;
            }
        } else if (blk == 2 || blk == 3) {
            float* dst = g_small + (blk == 2 ? R1TOFF : R2TOFF);
            for (int j = tid; j < 320; j += 256) {
                int ci = j >> 5, idx = (j & 31) >> 1;
                int g = idx >> 3, k = idx & 7;
                dst[j] = (k < 5) ? quantv(w[(5 * g + k) * 10 + ci], s) : 0.f;
            }
        } else if (blk <= 7) {
            int br = (blk - 4) >> 1;
            int half = (blk - 4) & 1;
            float* dst = g_qoa2 + br * 19600;
            int jb = half * 9800;
            for (int j = jb + tid; j < jb + 9800; j += 256) {
                int i4 = j / 560, rem = j - i4 * 560;
                int c = rem >> 3, t = (rem & 7) >> 1;
                dst[j] = quantv(w[c * 140 + i4 * 4 + t], s);
            }
        } else {
            float* dst = g_qob2 + (blk - 8) * 4320;
            for (int j = tid; j < 4320; j += 256) {
                int i4 = j / 240, rem = j - i4 * 240;
                int c = rem >> 3, t = (rem & 7) >> 1;
                int i = i4 * 4 + t;
                dst[j] = (i < 70) ? quantv(w[c * 70 + i], s) : 0.f;
            }
        }
    } else if (blk == 10) {
        int wrp = tid >> 5, l = tid & 31;
        if (wrp < 2) {
            const float* src = (wrp == 0) ? wo1c : wo2c;
            float m = (l < 30) ? fabsf(src[l]) : 0.f;
            #pragma unroll
            for (int s2 = 16; s2 > 0; s2 >>= 1)
                m = fmaxf(m, __shfl_xor_sync(0xffffffffu, m, s2));
            float sc = m / 127.f;
            float v = (l < 30) ? quantv(src[l], sc) : 0.f;
            g_small[QOCOFF + wrp * 64 + 2 * l]     = v;
            g_small[QOCOFF + wrp * 64 + 2 * l + 1] = v;
        }
    } else {
        fill_bn(bn1, 5,  g_small + A1OFF,  g_small + B1OFF);
        fill_bn(bn2, 10, g_small + A2OFF,  g_small + B2OFF);
        fill_bn(bnr1, 10, g_small + AR1OFF, g_small + BR1OFF);
        fill_bn(bnr2, 10, g_small + AR2OFF, g_small + BR2OFF);
        fill_bn(bno1a, 70, g_small + AOAOFF,      g_small + BOAOFF);
        fill_bn(bno2a, 70, g_small + AOAOFF + 70, g_small + BOAOFF + 70);
        fill_bn(bno1b, 30, g_small + AOBOFF,      g_small + BOBOFF);
        fill_bn(bno2b, 30, g_small + AOBOFF + 30, g_small + BOBOFF + 30);
        fill_bn(bno1c, 1, g_small + AOCOFF,     g_small + BOCOFF);
        fill_bn(bno2c, 1, g_small + AOCOFF + 1, g_small + BOCOFF + 1);
    }
}

// ---------------------------------------------------------------------------
// Per-warp workspace (floats), same aliasing map as R9.
//   X  @0     float4[256] (1024)   [T aliases X; A aliases X]
//   H1 @1024  float4[245] (980)    stride-49     [F aliases H1]
//   H2 @2004  float4[144] (576)    [B aliases H2]
#define XOFF  0
#define H1OFF 1024
#define H2OFF 2004
#define FOFF  1024
#define AOFF  0
#define BOFF  2004
#define WS_N  2580

#define NEG1X2 0xBF800000BF800000ULL
#define ABSM2  0x7FFFFFFF7FFFFFFFULL

__device__ __forceinline__ u64 ffma2_(u64 a, u64 b, u64 c) {
    u64 r;
    asm("fma.rn.f32x2 %0, %1, %2, %3;" : "=l"(r) : "l"(a), "l"(b), "l"(c));
    return r;
}
__device__ __forceinline__ u64 fadd2_(u64 a, u64 b) {
    u64 r;
    asm("add.rn.f32x2 %0, %1, %2;" : "=l"(r) : "l"(a), "l"(b));
    return r;
}
// acc += |u - w|   (FFMA2 diff, LOP3x2 abs on alu pipe, FADD2 acc)
__device__ __forceinline__ void accp(u64& acc, u64 u, u64 w) {
    acc = fadd2_(acc, ffma2_(w, NEG1X2, u) & ABSM2);
}

struct q4 { u64 a, b; };          // (e0,e1),(e2,e3)
__device__ __forceinline__ q4 qzero() { q4 z; z.a = 0ull; z.b = 0ull; return z; }
__device__ __forceinline__ void accq(q4& s, ulonglong2 u, u64 w) {
    accp(s.a, u.x, w);
    accp(s.b, u.y, w);
}
__device__ __forceinline__ q4 qadd(q4 x, q4 y) {
    q4 r; r.a = fadd2_(x.a, y.a); r.b = fadd2_(x.b, y.b); return r;
}
__device__ __forceinline__ float2 u2f(u64 v) {
    float2 f;
    asm("mov.b64 {%0, %1}, %2;" : "=f"(f.x), "=f"(f.y) : "l"(v));
    return f;
}
__device__ __forceinline__ float4 bnrelu_q(q4 s, float al, float be) {
    float2 p = u2f(s.a), q = u2f(s.b);
    return make_float4(fmaxf(fmaf(-p.x, al, be), 0.f),
                       fmaxf(fmaf(-p.y, al, be), 0.f),
                       fmaxf(fmaf(-q.x, al, be), 0.f),
                       fmaxf(fmaf(-q.y, al, be), 0.f));
}

#define ZERO4 make_float4(0.f, 0.f, 0.f, 0.f)

__global__ void __launch_bounds__(128) taunet_main(const float* __restrict__ x,
                                                   float* __restrict__ out, int nB)
{
    extern __shared__ __align__(16) float dsm[];
    float* s_small = dsm;

    for (int i = threadIdx.x; i < SMALL_N; i += 128) s_small[i] = g_small[i];
    __syncthreads();

    const int warp = threadIdx.x >> 5, lane = threadIdx.x & 31;
    float* ws = dsm + SMALL_N + warp * WS_N;
    float4*     X4f = (float4*)(ws + XOFF);
    ulonglong2* XU  = (ulonglong2*)(ws + XOFF);
    float4*     H1f = (float4*)(ws + H1OFF);
    ulonglong2* HU1 = (ulonglong2*)(ws + H1OFF);
    float4*     H2f = (float4*)(ws + H2OFF);
    ulonglong2* HU2 = (ulonglong2*)(ws + H2OFF);
    float4*     T4f = (float4*)(ws + XOFF);
    ulonglong2* TU  = (ulonglong2*)(ws + XOFF);
    float4*     F4f = (float4*)(ws + FOFF);
    ulonglong2* FU  = (ulonglong2*)(ws + FOFF);
    float4*     A4f = (float4*)(ws + AOFF);
    ulonglong2* AU  = (ulonglong2*)(ws + AOFF);
    float4*     B4f = (float4*)(ws + BOFF);

    // ---- per-lane o-layer slot precompute (float4-space indices, as R9) ----
    const int j2 = lane + 64, j3 = lane + 96;
    const int j4 = (lane + 128 < 140) ? lane + 128 : 139;
    const int oa2 = (j2 < 70) ? j2 : (2450 + (j2 - 70));
    const int oa3 = 2450 + (j3 - 70);
    const int oa4 = 2450 + (j4 - 70);
    const int d2 = (j2 < 70) ? j2 : (72 + (j2 - 70));
    const int d3 = 72 + (j3 - 70);
    const int d4 = 72 + (j4 - 70);
    const int jb1 = (lane + 32 < 60) ? lane + 32 : 59;
    const int obb0 = lane / 30, obc0 = lane - 30 * obb0;
    const int ob0 = obb0 * 540 + obc0;
    const int ob1 = 540 + (jb1 - 30);
    const int rp = lane >> 1, rg = lane & 1;

    const int nQ = (nB + 3) >> 2;
    const int gw = blockIdx.x * 4 + warp;
    const int stride = gridDim.x * 4;

    for (int q = gw; q < nQ; q += stride) {
        const int e0 = 4 * q;
        const int e1 = (e0 + 1 < nB) ? e0 + 1 : nB - 1;
        const int e2 = (e0 + 2 < nB) ? e0 + 2 : nB - 1;
        const int e3 = (e0 + 3 < nB) ? e0 + 3 : nB - 1;

        // ---- stage 4 input rows, transposed into float4-per-position ----
        {
            const float4* r0 = (const float4*)(x + (size_t)e0 * 256);
            const float4* r1 = (const float4*)(x + (size_t)e1 * 256);
            const float4* r2 = (const float4*)(x + (size_t)e2 * 256);
            const float4* r3 = (const float4*)(x + (size_t)e3 * 256);
            #pragma unroll
            for (int i = 0; i < 2; i++) {
                int m = lane + 32 * i;
                float4 a = __ldg(r0 + m);
                float4 b = __ldg(r1 + m);
                float4 c = __ldg(r2 + m);
                float4 d = __ldg(r3 + m);
                X4f[4 * m + 0] = make_float4(a.x, b.x, c.x, d.x);
                X4f[4 * m + 1] = make_float4(a.y, b.y, c.y, d.y);
                X4f[4 * m + 2] = make_float4(a.z, b.z, c.z, d.z);
                X4f[4 * m + 3] = make_float4(a.w, b.w, c.w, d.w);
            }
        }
        __syncwarp();

        // ---- pre1: 125 dual-position tasks (5ch x 25pd), K=13, stride 5 ----
        #pragma unroll 1
        for (int r = 0; r < 4; r++) {
            int idx = lane + 32 * r;
            if (idx < 125) {
                int c = idx / 25, pd = idx - 25 * c;
                int p0 = 2 * pd;
                bool dual = (pd < 24);
                u64 w[14];
                const ulonglong2* wv = (const ulonglong2*)(s_small + W1OFF + c * 32);
                #pragma unroll
                for (int i = 0; i < 7; i++) {
                    ulonglong2 t = wv[i];
                    w[2 * i] = t.x; w[2 * i + 1] = t.y;
                }
                const ulonglong2* xp = XU + 5 * p0;
                q4 A0 = qzero(), B0 = qzero(), A1 = qzero(), B1 = qzero();
                #pragma unroll
                for (int k = 0; k < 13; k++) {
                    ulonglong2 a = xp[k];
                    if (k & 1) accq(B0, a, w[k]); else accq(A0, a, w[k]);
                    if (k >= 5) {
                        if ((k - 5) & 1) accq(B1, a, w[k - 5]); else accq(A1, a, w[k - 5]);
                    }
                }
                if (dual) {
                    #pragma unroll
                    for (int k = 13; k < 18; k++) {
                        ulonglong2 a = xp[k];
                        if ((k - 5) & 1) accq(B1, a, w[k - 5]); else accq(A1, a, w[k - 5]);
                    }
                }
                float al = s_small[A1OFF + c], be = s_small[B1OFF + c];
                H1f[c * 49 + p0] = bnrelu_q(qadd(A0, B0), al, be);
                if (dual)
                    H1f[c * 49 + p0 + 1] = bnrelu_q(qadd(A1, B1), al, be);
            }
        }
        __syncwarp();

        // ---- pre2: 140 tasks (10ch x 14pos), 5cin x K=9, stride 3 ----
        #pragma unroll 1
        for (int r = 0; r < 5; r++) {
            int idx = lane + 32 * r;
            if (idx < 140) {
                int c = idx / 14, pp = idx - 14 * c;
                const ulonglong2* hp = HU1 + 3 * pp;
                q4 Aa = qzero(), Bb = qzero();
                #pragma unroll
                for (int ci = 0; ci < 5; ci++) {
                    const float* wbse = s_small + W2OFF + (c * 5 + ci) * 24;
                    const ulonglong2* wv = (const ulonglong2*)wbse;
                    ulonglong2 t0 = wv[0], t1 = wv[1], t2 = wv[2], t3 = wv[3];
                    u64 w8v = ((const u64*)wbse)[8];
                    u64 w[9] = {t0.x, t0.y, t1.x, t1.y, t2.x, t2.y, t3.x, t3.y, w8v};
                    const ulonglong2* hc = hp + ci * 49;
                    #pragma unroll
                    for (int k = 0; k < 9; k++) {
                        if (k & 1) accq(Bb, hc[k], w[k]); else accq(Aa, hc[k], w[k]);
                    }
                }
                H2f[c * 14 + pp] = bnrelu_q(qadd(Aa, Bb),
                                            s_small[A2OFF + c], s_small[B2OFF + c]);
            }
        }
        __syncwarp();

        // ---- r1: position-major, lanes 0..27 = (p, g); 5 channels each ----
        if (lane < 28) {
            q4 acc[5];
            #pragma unroll
            for (int j = 0; j < 5; j++) acc[j] = qzero();
            #pragma unroll
            for (int ci = 0; ci < 10; ci++) {
                ulonglong2 a = HU2[ci * 14 + rp];
                const float* wb2 = s_small + R1TOFF + ci * 32 + 16 * rg;
                const ulonglong2* wv = (const ulonglong2*)wb2;
                ulonglong2 t0 = wv[0], t1 = wv[1];
                u64 w4v = ((const u64*)wb2)[4];
                u64 wj[5] = {t0.x, t0.y, t1.x, t1.y, w4v};
                #pragma unroll
                for (int j = 0; j < 5; j++) accq(acc[j], a, wj[j]);
            }
            #pragma unroll
            for (int j = 0; j < 5; j++) {
                int c = 5 * rg + j;
                T4f[c * 14 + rp] = bnrelu_q(acc[j], s_small[AR1OFF + c], s_small[BR1OFF + c]);
            }
        }
        __syncwarp();

        // ---- r2 + residual: same mapping, F over dead H1 ----
        if (lane < 28) {
            q4 acc[5];
            #pragma unroll
            for (int j = 0; j < 5; j++) acc[j] = qzero();
            #pragma unroll
            for (int ci = 0; ci < 10; ci++) {
                ulonglong2 a = TU[ci * 14 + rp];
                const float* wb2 = s_small + R2TOFF + ci * 32 + 16 * rg;
                const ulonglong2* wv = (const ulonglong2*)wb2;
                ulonglong2 t0 = wv[0], t1 = wv[1];
                u64 w4v = ((const u64*)wb2)[4];
                u64 wj[5] = {t0.x, t0.y, t1.x, t1.y, w4v};
                #pragma unroll
                for (int j = 0; j < 5; j++) accq(acc[j], a, wj[j]);
            }
            #pragma unroll
            for (int j = 0; j < 5; j++) {
                int c = 5 * rg + j;
                float al = s_small[AR2OFF + c], be = s_small[BR2OFF + c];
                float4 h2v = H2f[c * 14 + rp];
                float2 p = u2f(acc[j].a), qv = u2f(acc[j].b);
                F4f[c * 14 + rp] = make_float4(
                    fmaxf(fmaf(-p.x,  al, be) + h2v.x, 0.f),
                    fmaxf(fmaf(-p.y,  al, be) + h2v.y, 0.f),
                    fmaxf(fmaf(-qv.x, al, be) + h2v.z, 0.f),
                    fmaxf(fmaf(-qv.y, al, be) + h2v.w, 0.f));
            }
        }
        if (lane < 4) F4f[140 + lane] = ZERO4;
        __syncwarp();

        // ---- oa: 5 channel slots x 4 packed elements ----
        {
            q4 acc[5];
            #pragma unroll
            for (int s = 0; s < 5; s++) acc[s] = qzero();

            const int slots[5] = {lane, lane + 32, oa2, oa3, oa4};
            const ulonglong2* QA2 = (const ulonglong2*)g_qoa2;

            #pragma unroll 5
            for (int i4 = 0; i4 < 35; i4++) {
                ulonglong2 u0 = FU[4 * i4 + 0];
                ulonglong2 u1 = FU[4 * i4 + 1];
                ulonglong2 u2 = FU[4 * i4 + 2];
                ulonglong2 u3 = FU[4 * i4 + 3];
                const int rowb = i4 * 140;
                #pragma unroll
                for (int s = 0; s < 5; s++) {
                    ulonglong2 wa = __ldg(QA2 + rowb + 2 * slots[s]);
                    ulonglong2 wb = __ldg(QA2 + rowb + 2 * slots[s] + 1);
                    accq(acc[s], u0, wa.x);
                    accq(acc[s], u1, wa.y);
                    accq(acc[s], u2, wb.x);
                    accq(acc[s], u3, wb.y);
                }
            }
            __syncwarp();   // F reads done before A overwrite of X region

            const int js[5] = {lane, lane + 32, j2, j3, j4};
            const int ds[5] = {lane, lane + 32, d2, d3, d4};
            #pragma unroll
            for (int s = 0; s < 5; s++) {
                A4f[ds[s]] = bnrelu_q(acc[s], s_small[AOAOFF + js[s]], s_small[BOAOFF + js[s]]);
            }
            if (lane < 2) {
                A4f[70 + lane]  = ZERO4;
                A4f[142 + lane] = ZERO4;
            }
        }
        __syncwarp();

        // ---- ob: 2 channel slots x 4 packed elements ----
        {
            q4 b0 = qzero(), b1 = qzero();
            const ulonglong2* QB2 = (const ulonglong2*)g_qob2;
            const ulonglong2* a0p = AU + obb0 * 72;
            const ulonglong2* a1p = AU + 72;

            #pragma unroll 6
            for (int i4 = 0; i4 < 18; i4++) {
                ulonglong2 wa = __ldg(QB2 + 2 * (i4 * 30 + ob0));
                ulonglong2 wb = __ldg(QB2 + 2 * (i4 * 30 + ob0) + 1);
                accq(b0, a0p[4 * i4 + 0], wa.x);
                accq(b0, a0p[4 * i4 + 1], wa.y);
                accq(b0, a0p[4 * i4 + 2], wb.x);
                accq(b0, a0p[4 * i4 + 3], wb.y);
                ulonglong2 wc = __ldg(QB2 + 2 * (i4 * 30 + ob1));
                ulonglong2 wd = __ldg(QB2 + 2 * (i4 * 30 + ob1) + 1);
                accq(b1, a1p[4 * i4 + 0], wc.x);
                accq(b1, a1p[4 * i4 + 1], wc.y);
                accq(b1, a1p[4 * i4 + 2], wd.x);
                accq(b1, a1p[4 * i4 + 3], wd.y);
            }
            __syncwarp();   // A reads done before B overwrite of H2 region

            B4f[obb0 * 32 + obc0] = bnrelu_q(b0, s_small[AOBOFF + lane], s_small[BOBOFF + lane]);
            B4f[32 + (jb1 - 30)]  = bnrelu_q(b1, s_small[AOBOFF + jb1], s_small[BOBOFF + jb1]);
            if (lane < 2) {
                B4f[30 + lane] = ZERO4;
                B4f[62 + lane] = ZERO4;
            }
        }
        __syncwarp();

        // ---- oc: 8 reductions (4 elems x 2 branches) ----
        {
            float w0 = s_small[QOCOFF + 2 * lane];
            float w1 = s_small[QOCOFF + 64 + 2 * lane];
            float4 p0 = B4f[lane];
            float4 p1 = B4f[32 + lane];
            float vA0 = fabsf(p0.x - w0), vA1 = fabsf(p0.y - w0);
            float vA2 = fabsf(p0.z - w0), vA3 = fabsf(p0.w - w0);
            float vI0 = fabsf(p1.x - w1), vI1 = fabsf(p1.y - w1);
            float vI2 = fabsf(p1.z - w1), vI3 = fabsf(p1.w - w1);
            #pragma unroll
            for (int s = 16; s > 0; s >>= 1) {
                vA0 += __shfl_xor_sync(0xffffffffu, vA0, s);
                vA1 += __shfl_xor_sync(0xffffffffu, vA1, s);
                vA2 += __shfl_xor_sync(0xffffffffu, vA2, s);
                vA3 += __shfl_xor_sync(0xffffffffu, vA3, s);
                vI0 += __shfl_xor_sync(0xffffffffu, vI0, s);
                vI1 += __shfl_xor_sync(0xffffffffu, vI1, s);
                vI2 += __shfl_xor_sync(0xffffffffu, vI2, s);
                vI3 += __shfl_xor_sync(0xffffffffu, vI3, s);
            }
            if (lane == 0) {
                float aA = s_small[AOCOFF],     bA = s_small[BOCOFF];
                float aI = s_small[AOCOFF + 1], bI = s_small[BOCOFF + 1];
                float vA[4] = {vA0, vA1, vA2, vA3};
                float vI[4] = {vI0, vI1, vI2, vI3};
                #pragma unroll
                for (int i = 0; i < 4; i++) {
                    if (e0 + i < nB) {
                        out[e0 + i]      = fmaxf(fmaf(-vA[i], aA, bA), 0.f);
                        out[nB + e0 + i] = fmaxf(fmaf(-vI[i], aI, bI), 0.f);
                    }
                }
            }
        }
        __syncwarp();   // B reads done before next iteration overwrites
    }
}

// ---------------------------------------------------------------------------
extern "C" void kernel_launch(void* const* d_in, const int* in_sizes, int n_in,
                              void* d_out, int out_size)
{
    const float* x     = (const float*)d_in[0];
    const float* w1    = (const float*)d_in[1];
    const float* bn1   = (const float*)d_in[2];
    const float* w2    = (const float*)d_in[3];
    const float* bn2   = (const float*)d_in[4];
    const float* wr1   = (const float*)d_in[5];
    const float* bnr1  = (const float*)d_in[6];
    const float* wr2   = (const float*)d_in[7];
    const float* bnr2  = (const float*)d_in[8];
    const float* wo1a  = (const float*)d_in[9];
    const float* bno1a = (const float*)d_in[10];
    const float* wo1b  = (const float*)d_in[11];
    const float* bno1b = (const float*)d_in[12];
    const float* wo1c  = (const float*)d_in[13];
    const float* bno1c = (const float*)d_in[14];
    const float* wo2a  = (const float*)d_in[15];
    const float* bno2a = (const float*)d_in[16];
    const float* wo2b  = (const float*)d_in[17];
    const float* bno2b = (const float*)d_in[18];
    const float* wo2c  = (const float*)d_in[19];
    const float* bno2c = (const float*)d_in[20];

    const int nB = in_sizes[0] / 256;
    const size_t smemBytes = (size_t)(SMALL_N + 4 * WS_N) * sizeof(float);   // 51696

    cudaFuncSetAttribute(taunet_main, cudaFuncAttributeMaxDynamicSharedMemorySize,
                         (int)smemBytes);

    setup_kernel<<<12, 256>>>(w1, w2, wr1, wr2, wo1a, wo1b, wo1c, wo2a, wo2b, wo2c,
                              bn1, bn2, bnr1, bnr2, bno1a, bno1b, bno1c,
                              bno2a, bno2b, bno2c);
    taunet_main<<<512, 128, smemBytes>>>(x, (float*)d_out, nB);
}

// round 13
// speedup vs baseline: 1.5215x; 1.5215x over previous
#include <cuda_runtime.h>

// ============================================================================
// AdderNet TauNet R13: R9 (best, warp-per-quad E=4) + channel-fastest lane
// mapping in pre1/pre2 (window LDS becomes broadcast; kills bank conflicts).
// ============================================================================

#define EPSV 1e-5f

// ---- s_small layout (floats), compact ----
#define W1OFF   0      // 5 x 16
#define W2OFF   80     // 50 x 12
#define R1TOFF  680    // 10ci x 16  (transposed: [ci][8g + j] = w[5g+j][ci])
#define R2TOFF  840    // 10ci x 16
#define A1OFF   1000
#define B1OFF   1005
#define A2OFF   1010
#define B2OFF   1020
#define AR1OFF  1030
#define BR1OFF  1040
#define AR2OFF  1050
#define BR2OFF  1060
#define AOAOFF  1070   // 140
#define BOAOFF  1210   // 140
#define AOBOFF  1350   // 60
#define BOBOFF  1410   // 60
#define AOCOFF  1470   // 2
#define BOCOFF  1472   // 2
#define QOCOFF  1474   // 64
#define SMALL_N 1540

__device__ float g_small[1544];
__device__ float g_qoa[2 * 35 * 70 * 4];   // [branch][i/4][c][4]
__device__ float g_qob[2 * 18 * 30 * 4];

__device__ __forceinline__ float quantv(float w, float s) {
    float t = fminf(fmaxf(w / s, -127.f), 127.f);
    return rintf(t) * s;
}

__device__ __forceinline__ void fill_bn(const float* bn, int c, float* A, float* Bt) {
    for (int i = threadIdx.x; i < c; i += blockDim.x) {
        float g = bn[i], b = bn[c + i], m = bn[2 * c + i], v = bn[3 * c + i];
        float al = g * rsqrtf(v + EPSV);
        A[i] = al;
        Bt[i] = b - m * al;
    }
}

// ---------------------------------------------------------------------------
__global__ void setup_kernel(
    const float* __restrict__ w1,   const float* __restrict__ w2,
    const float* __restrict__ wr1,  const float* __restrict__ wr2,
    const float* __restrict__ wo1a, const float* __restrict__ wo1b, const float* __restrict__ wo1c,
    const float* __restrict__ wo2a, const float* __restrict__ wo2b, const float* __restrict__ wo2c,
    const float* __restrict__ bn1,  const float* __restrict__ bn2,
    const float* __restrict__ bnr1, const float* __restrict__ bnr2,
    const float* __restrict__ bno1a, const float* __restrict__ bno1b, const float* __restrict__ bno1c,
    const float* __restrict__ bno2a, const float* __restrict__ bno2b, const float* __restrict__ bno2c)
{
    const int blk = blockIdx.x, tid = threadIdx.x;
    if (blk < 10) {
        const float* w; int n;
        switch (blk) {
            case 0: w = w1;   n = 65;   break;
            case 1: w = w2;   n = 450;  break;
            case 2: w = wr1;  n = 100;  break;
            case 3: w = wr2;  n = 100;  break;
            case 4: w = wo1a; n = 9800; break;
            case 5: w = wo2a; n = 9800; break;
            case 6: w = wo1b; n = 2100; break;
            case 7: w = wo2b; n = 2100; break;
            case 8: w = wo1c; n = 30;   break;
            default: w = wo2c; n = 30;  break;
        }
        __shared__ float red[256];
        float m = 0.f;
        for (int i = tid; i < n; i += 256) m = fmaxf(m, fabsf(w[i]));
        red[tid] = m;
        __syncthreads();
        for (int s = 128; s > 0; s >>= 1) {
            if (tid < s) red[tid] = fmaxf(red[tid], red[tid + s]);
            __syncthreads();
        }
        const float s = red[0] / 127.f;

        if (blk == 0) {
            for (int j = tid; j < 80; j += 256) {
                int c = j >> 4, k = j & 15;
                g_small[W1OFF + j] = (k < 13) ? quantv(w[c * 13 + k], s) : 0.f;
            }
        } else if (blk == 1) {
            for (int j = tid; j < 600; j += 256) {
                int row = j / 12, k = j - row * 12;
                g_small[W2OFF + j] = (k < 9) ? quantv(w[row * 9 + k], s) : 0.f;
            }
        } else if (blk == 2 || blk == 3) {
            // transposed: dst[ci*16 + 8g + k] = quant(w[(5g+k)*10 + ci]), k<5
            float* dst = g_small + (blk == 2 ? R1TOFF : R2TOFF);
            for (int j = tid; j < 160; j += 256) {
                int ci = j >> 4, rem = j & 15;
                int g = rem >> 3, k = rem & 7;
                int c = 5 * g + k;
                dst[j] = (k < 5) ? quantv(w[c * 10 + ci], s) : 0.f;
            }
        } else if (blk == 4 || blk == 5) {
            float* dst = g_qoa + (blk - 4) * 9800;
            for (int j = tid; j < 9800; j += 256) {
                int i4 = j / 280, rem = j - i4 * 280;
                int c = rem >> 2, t = rem & 3;
                dst[j] = quantv(w[c * 140 + i4 * 4 + t], s);
            }
        } else if (blk == 6 || blk == 7) {
            float* dst = g_qob + (blk - 6) * 2160;
            for (int j = tid; j < 2160; j += 256) {
                int i4 = j / 120, rem = j - i4 * 120;
                int c = rem >> 2, t = rem & 3;
                int i = i4 * 4 + t;
                dst[j] = (i < 70) ? quantv(w[c * 70 + i], s) : 0.f;
            }
        } else {
            float* dst = g_small + QOCOFF + (blk - 8) * 32;
            if (tid < 32) dst[tid] = (tid < 30) ? quantv(w[tid], s) : 0.f;
        }
    } else {
        fill_bn(bn1, 5,  g_small + A1OFF,  g_small + B1OFF);
        fill_bn(bn2, 10, g_small + A2OFF,  g_small + B2OFF);
        fill_bn(bnr1, 10, g_small + AR1OFF, g_small + BR1OFF);
        fill_bn(bnr2, 10, g_small + AR2OFF, g_small + BR2OFF);
        fill_bn(bno1a, 70, g_small + AOAOFF,      g_small + BOAOFF);
        fill_bn(bno2a, 70, g_small + AOAOFF + 70, g_small + BOAOFF + 70);
        fill_bn(bno1b, 30, g_small + AOBOFF,      g_small + BOBOFF);
        fill_bn(bno2b, 30, g_small + AOBOFF + 30, g_small + BOBOFF + 30);
        fill_bn(bno1c, 1, g_small + AOCOFF,     g_small + BOCOFF);
        fill_bn(bno2c, 1, g_small + AOCOFF + 1, g_small + BOCOFF + 1);
    }
}

// ---------------------------------------------------------------------------
// Per-warp workspace (floats). Activations float4 = (e0,e1,e2,e3).
//   X  @0     float4[256] (1024)   [T aliases X; A aliases X]
//   H1 @1024  float4[245] (980)    stride-49 rows  [F aliases H1]
//   H2 @2004  float4[144] (576)    [B aliases H2]
#define XOFF  0
#define H1OFF 1024
#define H2OFF 2004
#define FOFF  1024
#define AOFF  0
#define BOFF  2004
#define WS_N  2580

__device__ __forceinline__ void ld4(float* d, const float* s) {
    float4 v = *(const float4*)s;
    d[0] = v.x; d[1] = v.y; d[2] = v.z; d[3] = v.w;
}

// d = u - w as FFMA-imm (bit-identical)
__device__ __forceinline__ float fdiff(float u, float w) {
    float d;
    asm("fma.rn.f32 %0, %1, 0fBF800000, %2;" : "=f"(d) : "f"(w), "f"(u));
    return d;
}

__device__ __forceinline__ void acc4(float4& a, float4 u, float w) {
    a.x += fabsf(fdiff(u.x, w));
    a.y += fabsf(fdiff(u.y, w));
    a.z += fabsf(fdiff(u.z, w));
    a.w += fabsf(fdiff(u.w, w));
}

__device__ __forceinline__ float4 add4(float4 a, float4 b) {
    return make_float4(a.x + b.x, a.y + b.y, a.z + b.z, a.w + b.w);
}

__device__ __forceinline__ float4 bnrelu4(float4 a, float al, float be) {
    return make_float4(fmaxf(fmaf(-a.x, al, be), 0.f),
                       fmaxf(fmaf(-a.y, al, be), 0.f),
                       fmaxf(fmaf(-a.z, al, be), 0.f),
                       fmaxf(fmaf(-a.w, al, be), 0.f));
}

#define ZERO4 make_float4(0.f, 0.f, 0.f, 0.f)

__global__ void __launch_bounds__(128) taunet_main(const float* __restrict__ x,
                                                   float* __restrict__ out, int nB)
{
    __shared__ __align__(16) float s_small[SMALL_N];
    __shared__ __align__(16) float s_ws[4][WS_N];

    for (int i = threadIdx.x; i < SMALL_N; i += 128) s_small[i] = g_small[i];
    __syncthreads();

    const int warp = threadIdx.x >> 5, lane = threadIdx.x & 31;
    float* ws = s_ws[warp];
    float4* X4  = (float4*)(ws + XOFF);
    float4* H14 = (float4*)(ws + H1OFF);
    float4* H24 = (float4*)(ws + H2OFF);
    float4* T4  = (float4*)(ws + XOFF);
    float4* F4  = (float4*)(ws + FOFF);
    float4* A4  = (float4*)(ws + AOFF);
    float4* B4  = (float4*)(ws + BOFF);

    // ---- per-lane o-layer slot precompute ----
    const int j2 = lane + 64, j3 = lane + 96;
    const int j4 = (lane + 128 < 140) ? lane + 128 : 139;
    const int oa2 = (j2 < 70) ? j2 : (2450 + (j2 - 70));
    const int oa3 = 2450 + (j3 - 70);
    const int oa4 = 2450 + (j4 - 70);
    const int d2 = (j2 < 70) ? j2 : (72 + (j2 - 70));
    const int d3 = 72 + (j3 - 70);
    const int d4 = 72 + (j4 - 70);
    const int jb1 = (lane + 32 < 60) ? lane + 32 : 59;
    const int obb0 = lane / 30, obc0 = lane - 30 * obb0;
    const int ob0 = obb0 * 540 + obc0;
    const int ob1 = 540 + (jb1 - 30);
    // r1/r2 mapping: lanes 0..27 -> (p, g)
    const int rp = lane >> 1, rg = lane & 1;

    const int nQ = (nB + 3) >> 2;
    const int gw = blockIdx.x * 4 + warp;
    const int stride = gridDim.x * 4;

    for (int q = gw; q < nQ; q += stride) {
        const int e0 = 4 * q;
        const int e1 = (e0 + 1 < nB) ? e0 + 1 : nB - 1;
        const int e2 = (e0 + 2 < nB) ? e0 + 2 : nB - 1;
        const int e3 = (e0 + 3 < nB) ? e0 + 3 : nB - 1;

        // ---- stage 4 input rows, transposed into float4-per-position ----
        {
            const float4* r0 = (const float4*)(x + (size_t)e0 * 256);
            const float4* r1 = (const float4*)(x + (size_t)e1 * 256);
            const float4* r2 = (const float4*)(x + (size_t)e2 * 256);
            const float4* r3 = (const float4*)(x + (size_t)e3 * 256);
            #pragma unroll
            for (int i = 0; i < 2; i++) {
                int m = lane + 32 * i;
                float4 a = __ldg(r0 + m);
                float4 b = __ldg(r1 + m);
                float4 c = __ldg(r2 + m);
                float4 d = __ldg(r3 + m);
                X4[4 * m + 0] = make_float4(a.x, b.x, c.x, d.x);
                X4[4 * m + 1] = make_float4(a.y, b.y, c.y, d.y);
                X4[4 * m + 2] = make_float4(a.z, b.z, c.z, d.z);
                X4[4 * m + 3] = make_float4(a.w, b.w, c.w, d.w);
            }
        }
        __syncwarp();

        // ---- pre1: 125 dual-position tasks, CHANNEL-FASTEST lane map ----
        // idx -> (pd = idx/5, c = idx%5): 5 adjacent lanes share the window
        // (broadcast LDS), weights differ per lane (5 rows, cheap).
        #pragma unroll 1
        for (int r = 0; r < 4; r++) {
            int idx = lane + 32 * r;
            if (idx < 125) {
                int pd = idx / 5, c = idx - 5 * pd;
                int p0 = 2 * pd;
                bool dual = (pd < 24);
                float w[16];
                const float* wb = s_small + W1OFF + c * 16;
                ld4(w, wb); ld4(w + 4, wb + 4); ld4(w + 8, wb + 8); ld4(w + 12, wb + 12);
                const float4* xp = X4 + 5 * p0;
                float4 A0 = ZERO4, B0 = ZERO4, A1 = ZERO4, B1 = ZERO4;
                #pragma unroll
                for (int k = 0; k < 13; k++) {
                    float4 a = xp[k];
                    if (k & 1) acc4(B0, a, w[k]); else acc4(A0, a, w[k]);
                    if (k >= 5) {
                        if ((k - 5) & 1) acc4(B1, a, w[k - 5]); else acc4(A1, a, w[k - 5]);
                    }
                }
                if (dual) {
                    #pragma unroll
                    for (int k = 13; k < 18; k++) {
                        float4 a = xp[k];
                        if ((k - 5) & 1) acc4(B1, a, w[k - 5]); else acc4(A1, a, w[k - 5]);
                    }
                }
                float al = s_small[A1OFF + c], be = s_small[B1OFF + c];
                H14[c * 49 + p0] = bnrelu4(add4(A0, B0), al, be);
                if (dual)
                    H14[c * 49 + p0 + 1] = bnrelu4(add4(A1, B1), al, be);
            }
        }
        __syncwarp();

        // ---- pre2: 140 tasks, CHANNEL-FASTEST lane map ----
        // idx -> (pp = idx/10, c = idx%10): 10 adjacent lanes share window.
        #pragma unroll 1
        for (int r = 0; r < 5; r++) {
            int idx = lane + 32 * r;
            if (idx < 140) {
                int pp = idx / 10, c = idx - 10 * pp;
                const float4* hp = H14 + 3 * pp;
                float4 Aa = ZERO4, Bb = ZERO4;
                #pragma unroll
                for (int ci = 0; ci < 5; ci++) {
                    float w[12];
                    const float* wb = s_small + W2OFF + (c * 5 + ci) * 12;
                    ld4(w, wb); ld4(w + 4, wb + 4); ld4(w + 8, wb + 8);
                    const float4* hc = hp + ci * 49;
                    #pragma unroll
                    for (int k = 0; k < 9; k++) {
                        if (k & 1) acc4(Bb, hc[k], w[k]); else acc4(Aa, hc[k], w[k]);
                    }
                }
                H24[c * 14 + pp] = bnrelu4(add4(Aa, Bb), s_small[A2OFF + c], s_small[B2OFF + c]);
            }
        }
        __syncwarp();

        // ---- r1: position-major, lanes 0..27 = (p, g); 5 channels each ----
        if (lane < 28) {
            float4 acc[5];
            #pragma unroll
            for (int j = 0; j < 5; j++) acc[j] = ZERO4;
            const float* wt = s_small + R1TOFF + 8 * rg;
            #pragma unroll
            for (int ci = 0; ci < 10; ci++) {
                float4 a = H24[ci * 14 + rp];
                float w8[8];
                ld4(w8, wt + ci * 16); ld4(w8 + 4, wt + ci * 16 + 4);
                #pragma unroll
                for (int j = 0; j < 5; j++) acc4(acc[j], a, w8[j]);
            }
            #pragma unroll
            for (int j = 0; j < 5; j++) {
                int c = 5 * rg + j;
                T4[c * 14 + rp] = bnrelu4(acc[j], s_small[AR1OFF + c], s_small[BR1OFF + c]);
            }
        }
        __syncwarp();

        // ---- r2 + residual: same mapping, F over dead H1 ----
        if (lane < 28) {
            float4 acc[5];
            #pragma unroll
            for (int j = 0; j < 5; j++) acc[j] = ZERO4;
            const float* wt = s_small + R2TOFF + 8 * rg;
            #pragma unroll
            for (int ci = 0; ci < 10; ci++) {
                float4 a = T4[ci * 14 + rp];
                float w8[8];
                ld4(w8, wt + ci * 16); ld4(w8 + 4, wt + ci * 16 + 4);
                #pragma unroll
                for (int j = 0; j < 5; j++) acc4(acc[j], a, w8[j]);
            }
            #pragma unroll
            for (int j = 0; j < 5; j++) {
                int c = 5 * rg + j;
                float al = s_small[AR2OFF + c], be = s_small[BR2OFF + c];
                float4 h2v = H24[c * 14 + rp];
                float4 a = acc[j];
                F4[c * 14 + rp] = make_float4(
                    fmaxf(fmaf(-a.x, al, be) + h2v.x, 0.f),
                    fmaxf(fmaf(-a.y, al, be) + h2v.y, 0.f),
                    fmaxf(fmaf(-a.z, al, be) + h2v.z, 0.f),
                    fmaxf(fmaf(-a.w, al, be) + h2v.w, 0.f));
            }
        }
        if (lane < 4) F4[140 + lane] = ZERO4;
        __syncwarp();

        // ---- oa: 5 channel slots x 4 packed elements ----
        {
            float4 acc[5];
            #pragma unroll
            for (int s = 0; s < 5; s++) acc[s] = ZERO4;

            const int slots[5] = {lane, lane + 32, oa2, oa3, oa4};
            const float4* QA = (const float4*)g_qoa;

            #pragma unroll 5
            for (int i4 = 0; i4 < 35; i4++) {
                float4 u0 = F4[4 * i4 + 0];
                float4 u1 = F4[4 * i4 + 1];
                float4 u2 = F4[4 * i4 + 2];
                float4 u3 = F4[4 * i4 + 3];
                const float4* qrow = QA + i4 * 70;
                #pragma unroll
                for (int s = 0; s < 5; s++) {
                    float4 w = __ldg(qrow + slots[s]);
                    acc4(acc[s], u0, w.x);
                    acc4(acc[s], u1, w.y);
                    acc4(acc[s], u2, w.z);
                    acc4(acc[s], u3, w.w);
                }
            }
            __syncwarp();   // F reads done before A overwrite of X region

            const int js[5] = {lane, lane + 32, j2, j3, j4};
            const int ds[5] = {lane, lane + 32, d2, d3, d4};
            #pragma unroll
            for (int s = 0; s < 5; s++) {
                A4[ds[s]] = bnrelu4(acc[s], s_small[AOAOFF + js[s]], s_small[BOAOFF + js[s]]);
            }
            if (lane < 2) {
                A4[70 + lane]  = ZERO4;
                A4[142 + lane] = ZERO4;
            }
        }
        __syncwarp();

        // ---- ob: 2 channel slots x 4 packed elements ----
        {
            float4 b0 = ZERO4;
            float4 b1 = ZERO4;
            const float4* QB = (const float4*)g_qob;
            const float4* a0p = A4 + obb0 * 72;
            const float4* a1p = A4 + 72;

            #pragma unroll 6
            for (int i4 = 0; i4 < 18; i4++) {
                float4 w0 = __ldg(QB + i4 * 30 + ob0);
                acc4(b0, a0p[4 * i4 + 0], w0.x);
                acc4(b0, a0p[4 * i4 + 1], w0.y);
                acc4(b0, a0p[4 * i4 + 2], w0.z);
                acc4(b0, a0p[4 * i4 + 3], w0.w);
                float4 w1 = __ldg(QB + i4 * 30 + ob1);
                acc4(b1, a1p[4 * i4 + 0], w1.x);
                acc4(b1, a1p[4 * i4 + 1], w1.y);
                acc4(b1, a1p[4 * i4 + 2], w1.z);
                acc4(b1, a1p[4 * i4 + 3], w1.w);
            }
            __syncwarp();   // A reads done before B overwrite of H2 region

            B4[obb0 * 32 + obc0] = bnrelu4(b0, s_small[AOBOFF + lane], s_small[BOBOFF + lane]);
            B4[32 + (jb1 - 30)]  = bnrelu4(b1, s_small[AOBOFF + jb1], s_small[BOBOFF + jb1]);
            if (lane < 2) {
                B4[30 + lane] = ZERO4;
                B4[62 + lane] = ZERO4;
            }
        }
        __syncwarp();

        // ---- oc: 8 reductions (4 elems x 2 branches) ----
        {
            float w0 = s_small[QOCOFF + lane], w1 = s_small[QOCOFF + 32 + lane];
            float4 p0 = B4[lane];
            float4 p1 = B4[32 + lane];
            float vA0 = fabsf(fdiff(p0.x, w0)), vA1 = fabsf(fdiff(p0.y, w0));
            float vA2 = fabsf(fdiff(p0.z, w0)), vA3 = fabsf(fdiff(p0.w, w0));
            float vI0 = fabsf(fdiff(p1.x, w1)), vI1 = fabsf(fdiff(p1.y, w1));
            float vI2 = fabsf(fdiff(p1.z, w1)), vI3 = fabsf(fdiff(p1.w, w1));
            #pragma unroll
            for (int s = 16; s > 0; s >>= 1) {
                vA0 += __shfl_xor_sync(0xffffffffu, vA0, s);
                vA1 += __shfl_xor_sync(0xffffffffu, vA1, s);
                vA2 += __shfl_xor_sync(0xffffffffu, vA2, s);
                vA3 += __shfl_xor_sync(0xffffffffu, vA3, s);
                vI0 += __shfl_xor_sync(0xffffffffu, vI0, s);
                vI1 += __shfl_xor_sync(0xffffffffu, vI1, s);
                vI2 += __shfl_xor_sync(0xffffffffu, vI2, s);
                vI3 += __shfl_xor_sync(0xffffffffu, vI3, s);
            }
            if (lane == 0) {
                float aA = s_small[AOCOFF],     bA = s_small[BOCOFF];
                float aI = s_small[AOCOFF + 1], bI = s_small[BOCOFF + 1];
                float vA[4] = {vA0, vA1, vA2, vA3};
                float vI[4] = {vI0, vI1, vI2, vI3};
                #pragma unroll
                for (int i = 0; i < 4; i++) {
                    if (e0 + i < nB) {
                        out[e0 + i]      = fmaxf(fmaf(-vA[i], aA, bA), 0.f);
                        out[nB + e0 + i] = fmaxf(fmaf(-vI[i], aI, bI), 0.f);
                    }
                }
            }
        }
        __syncwarp();   // B reads done before next iteration overwrites
    }
}

// ---------------------------------------------------------------------------
extern "C" void kernel_launch(void* const* d_in, const int* in_sizes, int n_in,
                              void* d_out, int out_size)
{
    const float* x     = (const float*)d_in[0];
    const float* w1    = (const float*)d_in[1];
    const float* bn1   = (const float*)d_in[2];
    const float* w2    = (const float*)d_in[3];
    const float* bn2   = (const float*)d_in[4];
    const float* wr1   = (const float*)d_in[5];
    const float* bnr1  = (const float*)d_in[6];
    const float* wr2   = (const float*)d_in[7];
    const float* bnr2  = (const float*)d_in[8];
    const float* wo1a  = (const float*)d_in[9];
    const float* bno1a = (const float*)d_in[10];
    const float* wo1b  = (const float*)d_in[11];
    const float* bno1b = (const float*)d_in[12];
    const float* wo1c  = (const float*)d_in[13];
    const float* bno1c = (const float*)d_in[14];
    const float* wo2a  = (const float*)d_in[15];
    const float* bno2a = (const float*)d_in[16];
    const float* wo2b  = (const float*)d_in[17];
    const float* bno2b = (const float*)d_in[18];
    const float* wo2c  = (const float*)d_in[19];
    const float* bno2c = (const float*)d_in[20];

    const int nB = in_sizes[0] / 256;

    setup_kernel<<<11, 256>>>(w1, w2, wr1, wr2, wo1a, wo1b, wo1c, wo2a, wo2b, wo2c,
                              bn1, bn2, bnr1, bnr2, bno1a, bno1b, bno1c,
                              bno2a, bno2b, bno2c);
    taunet_main<<<512, 128>>>(x, (float*)d_out, nB);
}